// round 11
// baseline (speedup 1.0000x reference)
#include <cuda_runtime.h>
#include <cstdint>

#define NB 8192
#define NP 8192
#define NF 256
#define STAGES 2
#define ABLK 8192           // 64 rows x 32 k fp32
#define BBLK 16384          // 128 rows x 32 k fp32
#define STAGE_B (ABLK + BBLK)          // 24 KB
#define SMEM_BYTES (STAGES * STAGE_B)  // 48 KB
#define GKT 16              // 2 fused tiles x 8 k-steps

// ---------------- device scratch (allocation-free) ----------------
__device__ float g_xsq[NB];
__device__ float g_psq[NP];
// fragment-order permuted tf32: g_Xr [tm(128)][kb(8)][8KB], g_Pr [tn(64)][kb(8)][16KB]
__device__ __align__(1024) float g_Xr[(size_t)NB * NF];
__device__ __align__(1024) float g_Pr[(size_t)NP * NF];

__device__ __forceinline__ uint32_t smem_u32(const void* p) {
    uint32_t a;
    asm("{ .reg .u64 t; cvta.to.shared.u64 t, %1; cvt.u32.u64 %0, t; }" : "=r"(a) : "l"(p));
    return a;
}

// ---------------- prepass: tf32 round + permute + row norms ----------------
// A block (64 m x 32 k, 8KB): atom = 16m x 8k = 512B, idx = ak*4 + am (16 atoms)
//   off = idx*512 + ((rr&7)*4+(cc&3))*16 + ((rr>>3)|((cc>>2)<<1))*4
// B block (128 n x 32 k, 16KB): atom = 16n x 8k = 512B (two n8 subtiles), idx = ak*8 + pn
//   off = idx*512 + (nn*4+(cc&3))*16 + sub*8 + (cc>>2)*4
__global__ __launch_bounds__(256) void prep_kernel(const float* __restrict__ X,
                                                   const float* __restrict__ P) {
    int row = blockIdx.x;
    bool isP = row >= NB;
    int r = isP ? row - NB : row;
    int t = threadIdx.x;

    float v = (isP ? P : X)[(size_t)r * NF + t];
    uint32_t u;
    asm("cvt.rna.tf32.f32 %0, %1;" : "=r"(u) : "f"(v));

    int kb = t >> 5, kin = t & 31;
    int ak = kin >> 3, cc = kin & 7;
    char* base;
    uint32_t off;
    if (!isP) {
        int tile = r >> 6, rin = r & 63;
        base = (char*)g_Xr + (((size_t)tile * 8 + kb) << 13);
        int am = rin >> 4, rr = rin & 15;
        off = ((uint32_t)(ak * 4 + am) << 9)
            + (uint32_t)((rr & 7) * 4 + (cc & 3)) * 16u
            + ((uint32_t)((rr >> 3) | ((cc >> 2) << 1)) << 2);
    } else {
        int tile = r >> 7, rin = r & 127;
        base = (char*)g_Pr + (((size_t)tile * 8 + kb) << 14);
        int pn = rin >> 4, sub = (rin >> 3) & 1, nn = rin & 7;
        off = ((uint32_t)(ak * 8 + pn) << 9)
            + (uint32_t)(nn * 4 + (cc & 3)) * 16u
            + (uint32_t)(sub * 8)
            + ((uint32_t)(cc >> 2) << 2);
    }
    *reinterpret_cast<float*>(base + off) = __uint_as_float(u);

    float s = v * v;
    #pragma unroll
    for (int o = 16; o > 0; o >>= 1) s += __shfl_xor_sync(0xffffffffu, s, o);
    __shared__ float red[8];
    if ((t & 31) == 0) red[t >> 5] = s;
    __syncthreads();
    if (t == 0) {
        float tot = 0.f;
        #pragma unroll
        for (int i = 0; i < 8; i++) tot += red[i];
        (isP ? g_psq : g_xsq)[r] = tot;
    }
}

// ---------------- main kernel: 64x128 CTA tile, 4 warps of 64x32, 2 fused tiles ----------------
__global__ __launch_bounds__(128, 4) void gauss_mma_kernel(float* __restrict__ out) {
    extern __shared__ char sm[];
    const uint32_t sb = smem_u32(sm);

    // 4096 CTAs = 128 tm x 32 tn-pairs; supertile grouping for L2 reuse
    const int id = blockIdx.x;
    const int tnp = ((id >> 11) << 4) | (id & 15);
    const int tm  = (id & 2047) >> 4;
    const int tn0 = tnp << 1;
    const int tn1 = tn0 + 1;

    const int tid = threadIdx.x;
    const int w = tid >> 5, lane = tid & 31;
    const int wn = w;                     // 1(M) x 4(N); warp tile 64x32
    const int g = lane >> 2, tg = lane & 3;

    const char* gA  = (const char*)g_Xr + ((size_t)tm  * 8 << 13);
    const char* gB0 = (const char*)g_Pr + ((size_t)tn0 * 8 << 14);
    const char* gB1 = (const char*)g_Pr + ((size_t)tn1 * 8 << 14);

    auto issue = [&](int gk) {   // gk compile-time under full unroll
        const char* a = gA + ((size_t)(gk & 7) << 13) + tid * 64;
        const char* b = ((gk < 8) ? gB0 : gB1) + ((size_t)(gk & 7) << 14) + tid * 128;
        const uint32_t st = sb + (uint32_t)(gk & 1) * STAGE_B;
        const uint32_t soA = st + (uint32_t)tid * 64;
        const uint32_t soB = st + ABLK + (uint32_t)tid * 128;
        #pragma unroll
        for (int j = 0; j < 4; j++)
            asm volatile("cp.async.cg.shared.global [%0], [%1], 16;" :: "r"(soA + j * 16), "l"(a + j * 16));
        #pragma unroll
        for (int j = 0; j < 8; j++)
            asm volatile("cp.async.cg.shared.global [%0], [%1], 16;" :: "r"(soB + j * 16), "l"(b + j * 16));
        asm volatile("cp.async.commit_group;" ::: "memory");
    };

    float acc[4][4][4];
    #pragma unroll
    for (int mt = 0; mt < 4; mt++)
        #pragma unroll
        for (int nt = 0; nt < 4; nt++)
            #pragma unroll
            for (int q = 0; q < 4; q++) acc[mt][nt][q] = 0.f;

    const uint32_t laneOff = (uint32_t)lane * 16;
    uint32_t af[2][4][4];   // [buf][mt][a0..a3]
    uint32_t bf[2][2][4];   // [buf][pair][b0_lo, b1_lo, b0_hi, b1_hi]

    auto ldfrags = [&](int buf, uint32_t so, int ak) {
        #pragma unroll
        for (int mt = 0; mt < 4; mt++) {
            uint32_t addr = so + ((uint32_t)(ak * 4 + mt) << 9) + laneOff;
            asm volatile("ld.shared.v4.b32 {%0,%1,%2,%3}, [%4];"
                         : "=r"(af[buf][mt][0]), "=r"(af[buf][mt][1]),
                           "=r"(af[buf][mt][2]), "=r"(af[buf][mt][3]) : "r"(addr));
        }
        #pragma unroll
        for (int pp = 0; pp < 2; pp++) {
            uint32_t addr = so + ABLK + ((uint32_t)(ak * 8 + wn * 2 + pp) << 9) + laneOff;
            asm volatile("ld.shared.v4.b32 {%0,%1,%2,%3}, [%4];"
                         : "=r"(bf[buf][pp][0]), "=r"(bf[buf][pp][1]),
                           "=r"(bf[buf][pp][2]), "=r"(bf[buf][pp][3]) : "r"(addr));
        }
    };

    auto epilogue = [&](int tn) {
        const int orow0 = tm * 64 + g;
        const int ocol0 = tn * 128 + wn * 32 + 2 * tg;
        #pragma unroll
        for (int mt = 0; mt < 4; mt++) {
            const int r0 = orow0 + mt * 16;
            const float xs0 = g_xsq[r0];
            const float xs1 = g_xsq[r0 + 8];
            float* orow_a = out + (size_t)r0 * NP;
            float* orow_b = out + (size_t)(r0 + 8) * NP;
            #pragma unroll
            for (int nt = 0; nt < 4; nt++) {
                const int cc = ocol0 + nt * 8;
                const float p0 = g_psq[cc];
                const float p1 = g_psq[cc + 1];
                float d00 = fmaxf(fmaf(-2.f, acc[mt][nt][0], xs0 + p0), 1e-30f);
                float d01 = fmaxf(fmaf(-2.f, acc[mt][nt][1], xs0 + p1), 1e-30f);
                float d10 = fmaxf(fmaf(-2.f, acc[mt][nt][2], xs1 + p0), 1e-30f);
                float d11 = fmaxf(fmaf(-2.f, acc[mt][nt][3], xs1 + p1), 1e-30f);
                float2 v0 = make_float2(__expf(-0.5f * d00 * rsqrtf(d00)),
                                        __expf(-0.5f * d01 * rsqrtf(d01)));
                float2 v1 = make_float2(__expf(-0.5f * d10 * rsqrtf(d10)),
                                        __expf(-0.5f * d11 * rsqrtf(d11)));
                *reinterpret_cast<float2*>(orow_a + cc) = v0;
                *reinterpret_cast<float2*>(orow_b + cc) = v1;
            }
        }
    };

    // prologue: 2 stages in flight, stage 0 resident
    issue(0);
    issue(1);
    asm volatile("cp.async.wait_group 1;" ::: "memory");
    __syncthreads();
    ldfrags(0, sb, 0);

    #pragma unroll
    for (int gkt = 0; gkt < GKT; gkt++) {
        const uint32_t so = sb + (uint32_t)(gkt & 1) * STAGE_B;
        #pragma unroll
        for (int ak = 0; ak < 4; ak++) {
            if (ak < 3) {
                ldfrags((ak + 1) & 1, so, ak + 1);
            } else if (gkt + 1 < GKT) {
                // boundary: next-stage data ready, all reads of the about-to-be-
                // overwritten stage precede this barrier, then refill + issue.
                asm volatile("cp.async.wait_group 0;" ::: "memory");
                __syncthreads();
                ldfrags(0, sb + (uint32_t)((gkt + 1) & 1) * STAGE_B, 0);
                if (gkt + 2 < GKT) issue(gkt + 2);
            }
            const int cur = ak & 1;
            #pragma unroll
            for (int mt = 0; mt < 4; mt++)
                #pragma unroll
                for (int nt = 0; nt < 4; nt++) {
                    const int pp = nt >> 1, ss = (nt & 1) * 2;
                    asm volatile(
                        "mma.sync.aligned.m16n8k8.row.col.f32.tf32.tf32.f32 "
                        "{%0,%1,%2,%3}, {%4,%5,%6,%7}, {%8,%9}, {%0,%1,%2,%3};"
                        : "+f"(acc[mt][nt][0]), "+f"(acc[mt][nt][1]),
                          "+f"(acc[mt][nt][2]), "+f"(acc[mt][nt][3])
                        : "r"(af[cur][mt][0]), "r"(af[cur][mt][1]),
                          "r"(af[cur][mt][2]), "r"(af[cur][mt][3]),
                          "r"(bf[cur][pp][ss]), "r"(bf[cur][pp][ss + 1]));
                }
        }
        if (gkt == 7) {
            // tile 0 epilogue overlaps tile 1's in-flight loads + other CTAs
            epilogue(tn0);
            #pragma unroll
            for (int mt = 0; mt < 4; mt++)
                #pragma unroll
                for (int nt = 0; nt < 4; nt++)
                    #pragma unroll
                    for (int q = 0; q < 4; q++) acc[mt][nt][q] = 0.f;
        }
    }
    epilogue(tn1);
}

// ---------------- launch ----------------
extern "C" void kernel_launch(void* const* d_in, const int* in_sizes, int n_in,
                              void* d_out, int out_size) {
    const float* x = (const float*)d_in[0];   // [8192, 256]
    const float* p = (const float*)d_in[1];   // [8192, 256]
    float* out = (float*)d_out;               // [8192, 8192]

    static bool configured = false;
    if (!configured) {
        cudaFuncSetAttribute(gauss_mma_kernel,
                             cudaFuncAttributeMaxDynamicSharedMemorySize, SMEM_BYTES);
        configured = true;
    }

    prep_kernel<<<NB + NP, 256>>>(x, p);

    gauss_mma_kernel<<<(NB / 64) * (NP / 128) / 2, 128, SMEM_BYTES>>>(out);
}

// round 12
// speedup vs baseline: 1.5027x; 1.5027x over previous
#include <cuda_runtime.h>
#include <cstdint>

#define NB 8192
#define NP 8192
#define NF 256
#define BM 128
#define BN 128
#define STAGES 3
#define AKB 16384           // 128x32 fp32 block bytes (A or B)
#define STAGE_B (2 * AKB)   // 32 KB
#define SMEM_BYTES (STAGES * STAGE_B)  // 96 KB
#define GKT 16              // 2 fused tiles x 8 k-steps

// ---------------- device scratch (allocation-free) ----------------
__device__ float g_xsq[NB];
__device__ float g_psq[NP];
// fragment-order permuted tf32 copies: [tile(64)][kb(8)][16KB block]
__device__ __align__(1024) float g_Xr[(size_t)NB * NF];
__device__ __align__(1024) float g_Pr[(size_t)NP * NF];

__device__ __forceinline__ uint32_t smem_u32(const void* p) {
    uint32_t a;
    asm("{ .reg .u64 t; cvta.to.shared.u64 t, %1; cvt.u32.u64 %0, t; }" : "=r"(a) : "l"(p));
    return a;
}

// ---------------- norms: warp per row, coalesced float4 ----------------
__global__ __launch_bounds__(256) void norm_kernel(const float* __restrict__ X,
                                                   const float* __restrict__ P) {
    const bool isP = blockIdx.x >= (NB / 8);
    const int rbase = (isP ? blockIdx.x - NB / 8 : blockIdx.x) * 8;
    const int g = threadIdx.x & 31;
    const int r = rbase + (threadIdx.x >> 5);

    const float* src = (isP ? P : X) + (size_t)r * NF + g * 8;
    float4 v0 = *reinterpret_cast<const float4*>(src);
    float4 v1 = *reinterpret_cast<const float4*>(src + 4);
    float s = v0.x * v0.x + v0.y * v0.y + v0.z * v0.z + v0.w * v0.w
            + v1.x * v1.x + v1.y * v1.y + v1.z * v1.z + v1.w * v1.w;
    #pragma unroll
    for (int o = 16; o > 0; o >>= 1) s += __shfl_xor_sync(0xffffffffu, s, o);
    if (g == 0) (isP ? g_psq : g_xsq)[r] = s;
}

// ---------------- permute: staged 16KB block, coalesced in & out ----------------
// A block fwd map: (rin,kin): ak=kin>>3, cc=kin&7, am=rin>>4, rr=rin&15
//   off = (ak*8+am)*512 + ((rr&7)*4+(cc&3))*16 + ((rr>>3)|((cc>>2)<<1))*4
// B block fwd map: pn=rin>>4, sub=(rin>>3)&1, nn=rin&7
//   off = (ak*8+pn)*512 + (nn*4+(cc&3))*16 + sub*8 + (cc>>2)*4
__global__ __launch_bounds__(256) void perm_kernel(const float* __restrict__ X,
                                                   const float* __restrict__ P) {
    __shared__ float st[128][33];
    const bool isB = blockIdx.x >= 512;
    const int blk = isB ? blockIdx.x - 512 : blockIdx.x;
    const int tile = blk >> 3, kb = blk & 7;
    const float* src = (isB ? P : X) + (size_t)tile * 128 * NF + kb * 32;
    char* dst = (char*)(isB ? g_Pr : g_Xr) + ((size_t)blk << 14);
    const int t = threadIdx.x;

    #pragma unroll
    for (int i = 0; i < 4; i++) {
        int v = t * 4 + i;            // 0..1023 float4s
        int row = v >> 3, c4 = v & 7;
        float4 f = *reinterpret_cast<const float4*>(src + (size_t)row * NF + c4 * 4);
        uint32_t u0, u1, u2, u3;
        asm("cvt.rna.tf32.f32 %0, %1;" : "=r"(u0) : "f"(f.x));
        asm("cvt.rna.tf32.f32 %0, %1;" : "=r"(u1) : "f"(f.y));
        asm("cvt.rna.tf32.f32 %0, %1;" : "=r"(u2) : "f"(f.z));
        asm("cvt.rna.tf32.f32 %0, %1;" : "=r"(u3) : "f"(f.w));
        st[row][c4 * 4 + 0] = __uint_as_float(u0);
        st[row][c4 * 4 + 1] = __uint_as_float(u1);
        st[row][c4 * 4 + 2] = __uint_as_float(u2);
        st[row][c4 * 4 + 3] = __uint_as_float(u3);
    }
    __syncthreads();

    #pragma unroll
    for (int i = 0; i < 4; i++) {
        int j = i * 256 + t;          // chunk 0..1023, warp-coalesced stores
        int atom = j >> 5, lane = j & 31;
        int ak = atom >> 3, idx = atom & 7;
        int lo = lane >> 2, cc = (lane & 3) + ak * 8;
        float4 o;
        if (!isB) {
            o.x = st[idx * 16 + lo][cc];
            o.y = st[idx * 16 + 8 + lo][cc];
            o.z = st[idx * 16 + lo][cc + 4];
            o.w = st[idx * 16 + 8 + lo][cc + 4];
        } else {
            o.x = st[idx * 16 + lo][cc];
            o.y = st[idx * 16 + lo][cc + 4];
            o.z = st[idx * 16 + 8 + lo][cc];
            o.w = st[idx * 16 + 8 + lo][cc + 4];
        }
        *reinterpret_cast<float4*>(dst + (size_t)j * 16) = o;
    }
}

// ---------------- main kernel: 2 fused 128x128 tiles, MMA-first schedule ----------------
__global__ __launch_bounds__(256, 2) void gauss_mma_kernel(float* __restrict__ out) {
    extern __shared__ char sm[];
    const uint32_t sb = smem_u32(sm);

    const int id0 = blockIdx.x * 2;
    const int tn0 = ((id0 >> 10) << 4) | (id0 & 15);
    const int tm  = (id0 & 1023) >> 4;
    const int tn1 = tn0 + 1;

    const int tid = threadIdx.x;
    const int w = tid >> 5, lane = tid & 31;
    const int wm = w & 1, wn = w >> 1;      // 2(M) x 4(N); warp tile 64x32
    const int g = lane >> 2, tg = lane & 3;

    const char* gA  = (const char*)g_Xr + ((size_t)tm  * 8 << 14);
    const char* gB0 = (const char*)g_Pr + ((size_t)tn0 * 8 << 14);
    const char* gB1 = (const char*)g_Pr + ((size_t)tn1 * 8 << 14);

    auto issue = [&](int gk) {
        const char* a = gA + ((size_t)(gk & 7) << 14) + tid * 64;
        const char* b = ((gk < 8) ? gB0 : gB1) + ((size_t)(gk & 7) << 14) + tid * 64;
        const uint32_t so = sb + (uint32_t)(gk % 3) * STAGE_B + (uint32_t)tid * 64;
        #pragma unroll
        for (int j = 0; j < 4; j++) {
            asm volatile("cp.async.cg.shared.global [%0], [%1], 16;" :: "r"(so + j * 16), "l"(a + j * 16));
            asm volatile("cp.async.cg.shared.global [%0], [%1], 16;" :: "r"(so + AKB + j * 16), "l"(b + j * 16));
        }
        asm volatile("cp.async.commit_group;" ::: "memory");
    };

    float acc[4][4][4];
    #pragma unroll
    for (int mt = 0; mt < 4; mt++)
        #pragma unroll
        for (int nt = 0; nt < 4; nt++)
            #pragma unroll
            for (int q = 0; q < 4; q++) acc[mt][nt][q] = 0.f;

    const uint32_t laneOff = (uint32_t)lane * 16;
    uint32_t af[2][4][4];
    uint32_t bf[2][2][4];

    auto ldfrags = [&](int buf, uint32_t so, int ak) {
        #pragma unroll
        for (int mt = 0; mt < 4; mt++) {
            uint32_t addr = so + ((uint32_t)(ak * 8 + wm * 4 + mt) << 9) + laneOff;
            asm volatile("ld.shared.v4.b32 {%0,%1,%2,%3}, [%4];"
                         : "=r"(af[buf][mt][0]), "=r"(af[buf][mt][1]),
                           "=r"(af[buf][mt][2]), "=r"(af[buf][mt][3]) : "r"(addr));
        }
        #pragma unroll
        for (int pp = 0; pp < 2; pp++) {
            uint32_t addr = so + AKB + ((uint32_t)(ak * 8 + wn * 2 + pp) << 9) + laneOff;
            asm volatile("ld.shared.v4.b32 {%0,%1,%2,%3}, [%4];"
                         : "=r"(bf[buf][pp][0]), "=r"(bf[buf][pp][1]),
                           "=r"(bf[buf][pp][2]), "=r"(bf[buf][pp][3]) : "r"(addr));
        }
    };

    auto mma_half = [&](int cur, int mt0) {
        #pragma unroll
        for (int mt = mt0; mt < mt0 + 2; mt++)
            #pragma unroll
            for (int nt = 0; nt < 4; nt++) {
                const int pp = nt >> 1, ss = (nt & 1) * 2;
                asm volatile(
                    "mma.sync.aligned.m16n8k8.row.col.f32.tf32.tf32.f32 "
                    "{%0,%1,%2,%3}, {%4,%5,%6,%7}, {%8,%9}, {%0,%1,%2,%3};"
                    : "+f"(acc[mt][nt][0]), "+f"(acc[mt][nt][1]),
                      "+f"(acc[mt][nt][2]), "+f"(acc[mt][nt][3])
                    : "r"(af[cur][mt][0]), "r"(af[cur][mt][1]),
                      "r"(af[cur][mt][2]), "r"(af[cur][mt][3]),
                      "r"(bf[cur][pp][ss]), "r"(bf[cur][pp][ss + 1]));
            }
    };

    auto epilogue = [&](int tn) {
        const int orow0 = tm * BM + wm * 64 + g;
        const int ocol0 = tn * BN + wn * 32 + 2 * tg;
        #pragma unroll
        for (int mt = 0; mt < 4; mt++) {
            const int r0 = orow0 + mt * 16;
            const float xs0 = g_xsq[r0];
            const float xs1 = g_xsq[r0 + 8];
            float* orow_a = out + (size_t)r0 * NP;
            float* orow_b = out + (size_t)(r0 + 8) * NP;
            #pragma unroll
            for (int nt = 0; nt < 4; nt++) {
                const int cc = ocol0 + nt * 8;
                const float p0 = g_psq[cc];
                const float p1 = g_psq[cc + 1];
                float d00 = fmaxf(fmaf(-2.f, acc[mt][nt][0], xs0 + p0), 1e-30f);
                float d01 = fmaxf(fmaf(-2.f, acc[mt][nt][1], xs0 + p1), 1e-30f);
                float d10 = fmaxf(fmaf(-2.f, acc[mt][nt][2], xs1 + p0), 1e-30f);
                float d11 = fmaxf(fmaf(-2.f, acc[mt][nt][3], xs1 + p1), 1e-30f);
                float2 v0 = make_float2(__expf(-0.5f * d00 * rsqrtf(d00)),
                                        __expf(-0.5f * d01 * rsqrtf(d01)));
                float2 v1 = make_float2(__expf(-0.5f * d10 * rsqrtf(d10)),
                                        __expf(-0.5f * d11 * rsqrtf(d11)));
                *reinterpret_cast<float2*>(orow_a + cc) = v0;
                *reinterpret_cast<float2*>(orow_b + cc) = v1;
            }
        }
    };

    // prologue
    issue(0);
    issue(1);
    asm volatile("cp.async.wait_group 1;" ::: "memory");
    __syncthreads();
    ldfrags(0, sb, 0);

    #pragma unroll
    for (int gkt = 0; gkt < GKT; gkt++) {
        const uint32_t so = sb + (uint32_t)(gkt % 3) * STAGE_B;
        #pragma unroll
        for (int ak = 0; ak < 4; ak++) {
            const int cur = ak & 1;
            // first half: tensor pipe fills immediately after any barrier
            mma_half(cur, 0);
            if (ak == 0) {
                if (gkt + 2 < GKT) issue(gkt + 2);
            }
            if (ak < 3) {
                ldfrags(cur ^ 1, so, ak + 1);
            } else if (gkt + 1 < GKT) {
                if (gkt + 2 < GKT) {
                    asm volatile("cp.async.wait_group 1;" ::: "memory");
                } else {
                    asm volatile("cp.async.wait_group 0;" ::: "memory");
                }
                __syncthreads();
                ldfrags(0, sb + (uint32_t)((gkt + 1) % 3) * STAGE_B, 0);
            }
            // second half
            mma_half(cur, 2);
        }
        if (gkt == 7) {
            epilogue(tn0);
            #pragma unroll
            for (int mt = 0; mt < 4; mt++)
                #pragma unroll
                for (int nt = 0; nt < 4; nt++)
                    #pragma unroll
                    for (int q = 0; q < 4; q++) acc[mt][nt][q] = 0.f;
        }
    }
    epilogue(tn1);
}

// ---------------- launch ----------------
extern "C" void kernel_launch(void* const* d_in, const int* in_sizes, int n_in,
                              void* d_out, int out_size) {
    const float* x = (const float*)d_in[0];   // [8192, 256]
    const float* p = (const float*)d_in[1];   // [8192, 256]
    float* out = (float*)d_out;               // [8192, 8192]

    static bool configured = false;
    if (!configured) {
        cudaFuncSetAttribute(gauss_mma_kernel,
                             cudaFuncAttributeMaxDynamicSharedMemorySize, SMEM_BYTES);
        configured = true;
    }

    norm_kernel<<<(NB + NP) / 8, 256>>>(x, p);
    perm_kernel<<<1024, 256>>>(x, p);

    gauss_mma_kernel<<<(NB / BM) * (NP / BN) / 2, 256, SMEM_BYTES>>>(out);
}

// round 13
// speedup vs baseline: 2.3449x; 1.5605x over previous
#include <cuda_runtime.h>
#include <cuda_fp16.h>
#include <cstdint>

#define NB 8192
#define NP 8192
#define NF 256
#define BM 128
#define BN 128
#define STAGES 3
#define AKB 16384           // 128 rows x 64 k fp16 block bytes (A or B)
#define STAGE_B (2 * AKB)   // 32 KB
#define SMEM_BYTES (STAGES * STAGE_B)  // 96 KB
#define GKT 8               // 2 fused tiles x 4 k-blocks(64)

// ---------------- device scratch (allocation-free) ----------------
__device__ float g_xsq[NB];
__device__ float g_psq[NP];
// fragment-order permuted fp16: [tile(64)][kb(4)][16KB block]
__device__ __align__(1024) __half g_Xh[(size_t)NB * NF];
__device__ __align__(1024) __half g_Ph[(size_t)NP * NF];

__device__ __forceinline__ uint32_t smem_u32(const void* p) {
    uint32_t a;
    asm("{ .reg .u64 t; cvta.to.shared.u64 t, %1; cvt.u32.u64 %0, t; }" : "=r"(a) : "l"(p));
    return a;
}
__device__ __forceinline__ uint32_t pack_h2(float lo, float hi) {
    __half2 h = __floats2half2_rn(lo, hi);   // .x = lo (low 16 bits)
    return *reinterpret_cast<uint32_t*>(&h);
}

// ---------------- norms: warp per row, coalesced float4 ----------------
__global__ __launch_bounds__(256) void norm_kernel(const float* __restrict__ X,
                                                   const float* __restrict__ P) {
    const bool isP = blockIdx.x >= (NB / 8);
    const int rbase = (isP ? blockIdx.x - NB / 8 : blockIdx.x) * 8;
    const int g = threadIdx.x & 31;
    const int r = rbase + (threadIdx.x >> 5);

    const float* src = (isP ? P : X) + (size_t)r * NF + g * 8;
    float4 v0 = *reinterpret_cast<const float4*>(src);
    float4 v1 = *reinterpret_cast<const float4*>(src + 4);
    float s = v0.x * v0.x + v0.y * v0.y + v0.z * v0.z + v0.w * v0.w
            + v1.x * v1.x + v1.y * v1.y + v1.z * v1.z + v1.w * v1.w;
    #pragma unroll
    for (int o = 16; o > 0; o >>= 1) s += __shfl_xor_sync(0xffffffffu, s, o);
    if (g == 0) (isP ? g_psq : g_xsq)[r] = s;
}

// ---------------- permute: 128x64 fp32 staged -> fp16 fragment blocks ----------------
// A block (128m x 64k, 16KB): atom = 16m x 16k = 512B, idx = sk*8 + am (32 atoms)
//   lane (g,tg) 16B chunk = full m16n8k16 A fragment:
//   {(g,2tg),(g,2tg+1)} {(g+8,2tg),(g+8,2tg+1)} {(g,2tg+8),(g,2tg+9)} {(g+8,2tg+8),(g+8,2tg+9)}
// B block: atom = 16n x 16k = 512B pairing two n8 subtiles, idx = sk*8 + pn
//   chunk = sub0{(2tg,n),(2tg+1,n)}{(2tg+8,n),(2tg+9,n)} then sub1 for n+8
__global__ __launch_bounds__(256) void perm_kernel(const float* __restrict__ X,
                                                   const float* __restrict__ P) {
    __shared__ float st[128][65];
    const bool isB = blockIdx.x >= 256;
    const int blk = isB ? blockIdx.x - 256 : blockIdx.x;
    const int tile = blk >> 2, kb = blk & 3;
    const float* src = (isB ? P : X) + (size_t)tile * 128 * NF + kb * 64;
    char* dst = (char*)(isB ? g_Ph : g_Xh) + ((size_t)blk << 14);
    const int t = threadIdx.x;

    #pragma unroll
    for (int i = 0; i < 8; i++) {
        int v = i * 256 + t;              // 2048 float4s
        int row = v >> 4, c4 = v & 15;
        float4 f = *reinterpret_cast<const float4*>(src + (size_t)row * NF + c4 * 4);
        st[row][c4 * 4 + 0] = f.x;
        st[row][c4 * 4 + 1] = f.y;
        st[row][c4 * 4 + 2] = f.z;
        st[row][c4 * 4 + 3] = f.w;
    }
    __syncthreads();

    #pragma unroll
    for (int i = 0; i < 4; i++) {
        int j = i * 256 + t;              // 1024 chunks of 16B
        int atom = j >> 5, lane = j & 31;
        int sk = atom >> 3, idx = atom & 7;
        int lo = lane >> 2, tg = lane & 3;
        int c0 = sk * 16 + 2 * tg;
        uint4 o;
        if (!isB) {
            int r0 = idx * 16 + lo, r1 = r0 + 8;
            o.x = pack_h2(st[r0][c0],     st[r0][c0 + 1]);
            o.y = pack_h2(st[r1][c0],     st[r1][c0 + 1]);
            o.z = pack_h2(st[r0][c0 + 8], st[r0][c0 + 9]);
            o.w = pack_h2(st[r1][c0 + 8], st[r1][c0 + 9]);
        } else {
            int n0 = idx * 16 + lo, n1 = n0 + 8;
            o.x = pack_h2(st[n0][c0],     st[n0][c0 + 1]);
            o.y = pack_h2(st[n0][c0 + 8], st[n0][c0 + 9]);
            o.z = pack_h2(st[n1][c0],     st[n1][c0 + 1]);
            o.w = pack_h2(st[n1][c0 + 8], st[n1][c0 + 9]);
        }
        *reinterpret_cast<uint4*>(dst + (size_t)j * 16) = o;
    }
}

// ---------------- main kernel: fp16 m16n8k16, 2 fused 128x128 tiles ----------------
__global__ __launch_bounds__(256, 2) void gauss_mma_kernel(float* __restrict__ out) {
    extern __shared__ char sm[];
    const uint32_t sb = smem_u32(sm);

    const int id0 = blockIdx.x * 2;
    const int tn0 = ((id0 >> 10) << 4) | (id0 & 15);
    const int tm  = (id0 & 1023) >> 4;
    const int tn1 = tn0 + 1;

    const int tid = threadIdx.x;
    const int w = tid >> 5, lane = tid & 31;
    const int wm = w & 1, wn = w >> 1;      // 2(M) x 4(N); warp tile 64x32
    const int g = lane >> 2, tg = lane & 3;

    const char* gA  = (const char*)g_Xh + ((size_t)tm  << 16);
    const char* gB0 = (const char*)g_Ph + ((size_t)tn0 << 16);
    const char* gB1 = (const char*)g_Ph + ((size_t)tn1 << 16);

    auto issue = [&](int gk) {   // gk compile-time under full unroll
        const char* a = gA + ((size_t)(gk & 3) << 14) + tid * 64;
        const char* b = ((gk < 4) ? gB0 : gB1) + ((size_t)(gk & 3) << 14) + tid * 64;
        const uint32_t so = sb + (uint32_t)(gk % 3) * STAGE_B + (uint32_t)tid * 64;
        #pragma unroll
        for (int j = 0; j < 4; j++) {
            asm volatile("cp.async.cg.shared.global [%0], [%1], 16;" :: "r"(so + j * 16), "l"(a + j * 16));
            asm volatile("cp.async.cg.shared.global [%0], [%1], 16;" :: "r"(so + AKB + j * 16), "l"(b + j * 16));
        }
        asm volatile("cp.async.commit_group;" ::: "memory");
    };

    float acc[4][4][4];
    #pragma unroll
    for (int mt = 0; mt < 4; mt++)
        #pragma unroll
        for (int nt = 0; nt < 4; nt++)
            #pragma unroll
            for (int q = 0; q < 4; q++) acc[mt][nt][q] = 0.f;

    const uint32_t laneOff = (uint32_t)lane * 16;
    uint32_t af[2][4][4];   // [buf][mt][a0..a3]
    uint32_t bf[2][2][4];   // [buf][pair][sub0_b0, sub0_b1, sub1_b0, sub1_b1]

    auto ldfrags = [&](int buf, uint32_t so, int sk) {
        #pragma unroll
        for (int mt = 0; mt < 4; mt++) {
            uint32_t addr = so + ((uint32_t)(sk * 8 + wm * 4 + mt) << 9) + laneOff;
            asm volatile("ld.shared.v4.b32 {%0,%1,%2,%3}, [%4];"
                         : "=r"(af[buf][mt][0]), "=r"(af[buf][mt][1]),
                           "=r"(af[buf][mt][2]), "=r"(af[buf][mt][3]) : "r"(addr));
        }
        #pragma unroll
        for (int pp = 0; pp < 2; pp++) {
            uint32_t addr = so + AKB + ((uint32_t)(sk * 8 + wn * 2 + pp) << 9) + laneOff;
            asm volatile("ld.shared.v4.b32 {%0,%1,%2,%3}, [%4];"
                         : "=r"(bf[buf][pp][0]), "=r"(bf[buf][pp][1]),
                           "=r"(bf[buf][pp][2]), "=r"(bf[buf][pp][3]) : "r"(addr));
        }
    };

    auto mma_half = [&](int cur, int mt0) {
        #pragma unroll
        for (int mt = mt0; mt < mt0 + 2; mt++)
            #pragma unroll
            for (int nt = 0; nt < 4; nt++) {
                const int pp = nt >> 1, ss = (nt & 1) * 2;
                asm volatile(
                    "mma.sync.aligned.m16n8k16.row.col.f32.f16.f16.f32 "
                    "{%0,%1,%2,%3}, {%4,%5,%6,%7}, {%8,%9}, {%0,%1,%2,%3};"
                    : "+f"(acc[mt][nt][0]), "+f"(acc[mt][nt][1]),
                      "+f"(acc[mt][nt][2]), "+f"(acc[mt][nt][3])
                    : "r"(af[cur][mt][0]), "r"(af[cur][mt][1]),
                      "r"(af[cur][mt][2]), "r"(af[cur][mt][3]),
                      "r"(bf[cur][pp][ss]), "r"(bf[cur][pp][ss + 1]));
            }
    };

    auto epilogue = [&](int tn) {
        const int orow0 = tm * BM + wm * 64 + g;
        const int ocol0 = tn * BN + wn * 32 + 2 * tg;
        #pragma unroll
        for (int mt = 0; mt < 4; mt++) {
            const int r0 = orow0 + mt * 16;
            const float xs0 = g_xsq[r0];
            const float xs1 = g_xsq[r0 + 8];
            float* orow_a = out + (size_t)r0 * NP;
            float* orow_b = out + (size_t)(r0 + 8) * NP;
            #pragma unroll
            for (int nt = 0; nt < 4; nt++) {
                const int cc = ocol0 + nt * 8;
                const float p0 = g_psq[cc];
                const float p1 = g_psq[cc + 1];
                float d00 = fmaxf(fmaf(-2.f, acc[mt][nt][0], xs0 + p0), 1e-30f);
                float d01 = fmaxf(fmaf(-2.f, acc[mt][nt][1], xs0 + p1), 1e-30f);
                float d10 = fmaxf(fmaf(-2.f, acc[mt][nt][2], xs1 + p0), 1e-30f);
                float d11 = fmaxf(fmaf(-2.f, acc[mt][nt][3], xs1 + p1), 1e-30f);
                float2 v0 = make_float2(__expf(-0.5f * d00 * rsqrtf(d00)),
                                        __expf(-0.5f * d01 * rsqrtf(d01)));
                float2 v1 = make_float2(__expf(-0.5f * d10 * rsqrtf(d10)),
                                        __expf(-0.5f * d11 * rsqrtf(d11)));
                *reinterpret_cast<float2*>(orow_a + cc) = v0;
                *reinterpret_cast<float2*>(orow_b + cc) = v1;
            }
        }
    };

    // prologue
    issue(0);
    issue(1);
    asm volatile("cp.async.wait_group 1;" ::: "memory");
    __syncthreads();
    ldfrags(0, sb, 0);

    #pragma unroll
    for (int gkt = 0; gkt < GKT; gkt++) {
        const uint32_t so = sb + (uint32_t)(gkt % 3) * STAGE_B;
        #pragma unroll
        for (int sk = 0; sk < 4; sk++) {
            const int cur = sk & 1;
            mma_half(cur, 0);                       // tensor pipe fills first
            if (sk == 0) {
                if (gkt + 2 < GKT) issue(gkt + 2);
            }
            if (sk < 3) {
                ldfrags(cur ^ 1, so, sk + 1);
            } else if (gkt + 1 < GKT) {
                if (gkt + 2 < GKT) {
                    asm volatile("cp.async.wait_group 1;" ::: "memory");
                } else {
                    asm volatile("cp.async.wait_group 0;" ::: "memory");
                }
                __syncthreads();
                ldfrags(0, sb + (uint32_t)((gkt + 1) % 3) * STAGE_B, 0);
            }
            mma_half(cur, 2);
        }
        if (gkt == 3) {
            epilogue(tn0);                          // overlaps tile 1's loads
            #pragma unroll
            for (int mt = 0; mt < 4; mt++)
                #pragma unroll
                for (int nt = 0; nt < 4; nt++)
                    #pragma unroll
                    for (int q = 0; q < 4; q++) acc[mt][nt][q] = 0.f;
        }
    }
    epilogue(tn1);
}

// ---------------- launch ----------------
extern "C" void kernel_launch(void* const* d_in, const int* in_sizes, int n_in,
                              void* d_out, int out_size) {
    const float* x = (const float*)d_in[0];   // [8192, 256]
    const float* p = (const float*)d_in[1];   // [8192, 256]
    float* out = (float*)d_out;               // [8192, 8192]

    static bool configured = false;
    if (!configured) {
        cudaFuncSetAttribute(gauss_mma_kernel,
                             cudaFuncAttributeMaxDynamicSharedMemorySize, SMEM_BYTES);
        configured = true;
    }

    norm_kernel<<<(NB + NP) / 8, 256>>>(x, p);
    perm_kernel<<<512, 256>>>(x, p);

    gauss_mma_kernel<<<(NB / BM) * (NP / BN) / 2, 256, SMEM_BYTES>>>(out);
}